// round 1
// baseline (speedup 1.0000x reference)
#include <cuda_runtime.h>
#include <math.h>

// Problem constants
#define DM 2048     // d_model
#define HID 8192    // hidden
#define NE 8        // experts
#define STOK 8192   // tokens (4*2048)
#define CAPE 2048   // capacity per expert

// ---------------- scratch (device globals; no allocations allowed) -----------
__device__ float g_disp[(size_t)NE * CAPE * DM];     // 128 MB, zero-init
__device__ float g_h[(size_t)NE * CAPE * HID];       // 512 MB
__device__ float g_eo[(size_t)NE * CAPE * DM];       // 128 MB
__device__ int   g_idx[STOK * 2];
__device__ float g_gate[STOK * 2];
__device__ int   g_pos[STOK * 2];                    // -1 => dropped
__device__ float g_gv[STOK * 2];                     // gate * valid

// ---------------- gate: logits -> softmax -> top2 -> normalize ---------------
__global__ void gate_kernel(const float* __restrict__ x, const float* __restrict__ wg)
{
    int gw   = (blockIdx.x * blockDim.x + threadIdx.x) >> 5;   // one warp per token
    int lane = threadIdx.x & 31;
    if (gw >= STOK) return;
    const float* xr = x + (size_t)gw * DM;
    float acc[NE];
#pragma unroll
    for (int e = 0; e < NE; e++) acc[e] = 0.f;
    for (int d = lane; d < DM; d += 32) {
        float xv = __ldg(xr + d);
        const float4* w = reinterpret_cast<const float4*>(wg + (size_t)d * NE);
        float4 w0 = __ldg(w), w1 = __ldg(w + 1);
        acc[0] = fmaf(xv, w0.x, acc[0]); acc[1] = fmaf(xv, w0.y, acc[1]);
        acc[2] = fmaf(xv, w0.z, acc[2]); acc[3] = fmaf(xv, w0.w, acc[3]);
        acc[4] = fmaf(xv, w1.x, acc[4]); acc[5] = fmaf(xv, w1.y, acc[5]);
        acc[6] = fmaf(xv, w1.z, acc[6]); acc[7] = fmaf(xv, w1.w, acc[7]);
    }
#pragma unroll
    for (int off = 16; off > 0; off >>= 1)
#pragma unroll
        for (int e = 0; e < NE; e++)
            acc[e] += __shfl_down_sync(0xffffffffu, acc[e], off);
    if (lane == 0) {
        float mx = acc[0];
#pragma unroll
        for (int e = 1; e < NE; e++) mx = fmaxf(mx, acc[e]);
        float p[NE]; float sum = 0.f;
#pragma unroll
        for (int e = 0; e < NE; e++) { p[e] = expf(acc[e] - mx); sum += p[e]; }
        float inv = 1.f / sum;
#pragma unroll
        for (int e = 0; e < NE; e++) p[e] *= inv;
        int i1 = 0;
#pragma unroll
        for (int e = 1; e < NE; e++) if (p[e] > p[i1]) i1 = e;   // ties: lowest index
        int i2 = (i1 == 0) ? 1 : 0;
#pragma unroll
        for (int e = 0; e < NE; e++) if (e != i1 && p[e] > p[i2]) i2 = e;
        float denom = fmaxf(p[i1] + p[i2], 1e-9f);
        g_idx[gw * 2 + 0] = i1;            g_idx[gw * 2 + 1] = i2;
        g_gate[gw * 2 + 0] = p[i1] / denom; g_gate[gw * 2 + 1] = p[i2] / denom;
    }
}

// ---------------- positions: order-exact per-expert cumsum -------------------
// One block per expert. Scans slot 0 over all tokens in order, then slot 1,
// carrying the running count (matches tutel cumsum + counts carryover).
__global__ void pos_kernel()
{
    int e = blockIdx.x;
    __shared__ int sc[1024];
    int base = 0;
    for (int s = 0; s < 2; ++s) {
        for (int chunk = 0; chunk < STOK; chunk += 1024) {
            int t = chunk + threadIdx.x;
            int m = (g_idx[t * 2 + s] == e) ? 1 : 0;
            sc[threadIdx.x] = m;
            __syncthreads();
            for (int off = 1; off < 1024; off <<= 1) {
                int v = (threadIdx.x >= off) ? sc[threadIdx.x - off] : 0;
                __syncthreads();
                sc[threadIdx.x] += v;
                __syncthreads();
            }
            if (m) {
                int p = base + sc[threadIdx.x] - 1;
                if (p < CAPE) { g_pos[t * 2 + s] = p;  g_gv[t * 2 + s] = g_gate[t * 2 + s]; }
                else          { g_pos[t * 2 + s] = -1; g_gv[t * 2 + s] = 0.f; }
            }
            base += sc[1023];
            __syncthreads();
        }
    }
}

// ---------------- dispatch: scatter token rows into expert buffers -----------
__global__ void dispatch_kernel(const float* __restrict__ x)
{
    int ts = blockIdx.x;
    int t = ts >> 1, s = ts & 1;
    int p = g_pos[t * 2 + s];
    if (p < 0) return;
    int e = g_idx[t * 2 + s];
    const float4* src = reinterpret_cast<const float4*>(x + (size_t)t * DM);
    float4* dst = reinterpret_cast<float4*>(g_disp + ((size_t)e * CAPE + p) * DM);
    for (int i = threadIdx.x; i < DM / 4; i += blockDim.x) dst[i] = src[i];
}

// ---------------- batched fp32 GEMM: C = A@B + bias (optional exact gelu) ----
// 128x128 tile, BK=16, 256 threads, 8x8 per-thread microtile, global->reg prefetch.
template <bool GELU>
__global__ void __launch_bounds__(256)
gemm_kernel(const float* __restrict__ Ab, const float* __restrict__ Bb,
            const float* __restrict__ biasb, float* __restrict__ Cb,
            int M, int N, int Kd)
{
    const int BK = 16;
    __shared__ float As[BK][128];
    __shared__ float Bs[BK][128];

    int z = blockIdx.z;
    const float* A    = Ab    + (size_t)z * M * Kd;
    const float* B    = Bb    + (size_t)z * Kd * N;
    const float* bias = biasb + (size_t)z * N;
    float*       Cm   = Cb    + (size_t)z * M * N;

    int tid  = threadIdx.x;
    int brow = blockIdx.y * 128;
    int bcol = blockIdx.x * 128;

    int a_r = tid >> 2;          // 0..63 (rows a_r and a_r+64)
    int a_k = (tid & 3) << 2;    // 0,4,8,12
    int b_k = tid >> 5;          // 0..7  (k rows b_k and b_k+8)
    int b_n = (tid & 31) << 2;   // 0..124

    int ty = tid >> 4;           // 0..15
    int tx = tid & 15;           // 0..15

    float acc[8][8];
#pragma unroll
    for (int i = 0; i < 8; i++)
#pragma unroll
        for (int j = 0; j < 8; j++) acc[i][j] = 0.f;

    int ntiles = Kd / BK;
    float4 pa0, pa1, pb0, pb1;

    {   // tile 0 load
        const float* Ap = A + (size_t)(brow + a_r) * Kd + a_k;
        pa0 = *reinterpret_cast<const float4*>(Ap);
        pa1 = *reinterpret_cast<const float4*>(Ap + (size_t)64 * Kd);
        const float* Bp = B + (size_t)b_k * N + bcol + b_n;
        pb0 = *reinterpret_cast<const float4*>(Bp);
        pb1 = *reinterpret_cast<const float4*>(Bp + (size_t)8 * N);
    }
    As[a_k + 0][a_r] = pa0.x; As[a_k + 1][a_r] = pa0.y;
    As[a_k + 2][a_r] = pa0.z; As[a_k + 3][a_r] = pa0.w;
    As[a_k + 0][a_r + 64] = pa1.x; As[a_k + 1][a_r + 64] = pa1.y;
    As[a_k + 2][a_r + 64] = pa1.z; As[a_k + 3][a_r + 64] = pa1.w;
    *reinterpret_cast<float4*>(&Bs[b_k][b_n])     = pb0;
    *reinterpret_cast<float4*>(&Bs[b_k + 8][b_n]) = pb1;
    __syncthreads();

    for (int t = 0; t < ntiles; ++t) {
        if (t + 1 < ntiles) {   // prefetch next tile into registers
            int k0 = (t + 1) * BK;
            const float* Ap = A + (size_t)(brow + a_r) * Kd + k0 + a_k;
            pa0 = *reinterpret_cast<const float4*>(Ap);
            pa1 = *reinterpret_cast<const float4*>(Ap + (size_t)64 * Kd);
            const float* Bp = B + (size_t)(k0 + b_k) * N + bcol + b_n;
            pb0 = *reinterpret_cast<const float4*>(Bp);
            pb1 = *reinterpret_cast<const float4*>(Bp + (size_t)8 * N);
        }
#pragma unroll
        for (int kk = 0; kk < BK; ++kk) {
            float a[8], b[8];
            *reinterpret_cast<float4*>(&a[0]) = *reinterpret_cast<const float4*>(&As[kk][ty * 8]);
            *reinterpret_cast<float4*>(&a[4]) = *reinterpret_cast<const float4*>(&As[kk][ty * 8 + 4]);
            *reinterpret_cast<float4*>(&b[0]) = *reinterpret_cast<const float4*>(&Bs[kk][tx * 8]);
            *reinterpret_cast<float4*>(&b[4]) = *reinterpret_cast<const float4*>(&Bs[kk][tx * 8 + 4]);
#pragma unroll
            for (int i = 0; i < 8; i++)
#pragma unroll
                for (int j = 0; j < 8; j++)
                    acc[i][j] = fmaf(a[i], b[j], acc[i][j]);
        }
        __syncthreads();
        if (t + 1 < ntiles) {
            As[a_k + 0][a_r] = pa0.x; As[a_k + 1][a_r] = pa0.y;
            As[a_k + 2][a_r] = pa0.z; As[a_k + 3][a_r] = pa0.w;
            As[a_k + 0][a_r + 64] = pa1.x; As[a_k + 1][a_r + 64] = pa1.y;
            As[a_k + 2][a_r + 64] = pa1.z; As[a_k + 3][a_r + 64] = pa1.w;
            *reinterpret_cast<float4*>(&Bs[b_k][b_n])     = pb0;
            *reinterpret_cast<float4*>(&Bs[b_k + 8][b_n]) = pb1;
            __syncthreads();
        }
    }

    // epilogue: + bias, optional exact gelu
    float bv[8];
#pragma unroll
    for (int j = 0; j < 8; j++) bv[j] = bias[bcol + tx * 8 + j];
#pragma unroll
    for (int i = 0; i < 8; i++) {
        float* Crow = Cm + (size_t)(brow + ty * 8 + i) * N + bcol + tx * 8;
#pragma unroll
        for (int j = 0; j < 8; j += 4) {
            float4 v;
            v.x = acc[i][j + 0] + bv[j + 0];
            v.y = acc[i][j + 1] + bv[j + 1];
            v.z = acc[i][j + 2] + bv[j + 2];
            v.w = acc[i][j + 3] + bv[j + 3];
            if (GELU) {
                v.x = 0.5f * v.x * (1.f + erff(v.x * 0.70710678118654752f));
                v.y = 0.5f * v.y * (1.f + erff(v.y * 0.70710678118654752f));
                v.z = 0.5f * v.z * (1.f + erff(v.z * 0.70710678118654752f));
                v.w = 0.5f * v.w * (1.f + erff(v.w * 0.70710678118654752f));
            }
            *reinterpret_cast<float4*>(Crow + j) = v;
        }
    }
}

// ---------------- combine: y = sum_s gv_s * eo[idx_s, pos_s] -----------------
__global__ void combine_kernel(float* __restrict__ y)
{
    int t = blockIdx.x;
    int e0 = g_idx[t * 2], e1 = g_idx[t * 2 + 1];
    int p0 = g_pos[t * 2], p1 = g_pos[t * 2 + 1];
    float w0 = g_gv[t * 2], w1 = g_gv[t * 2 + 1];
    const float* r0 = (p0 >= 0) ? g_eo + ((size_t)e0 * CAPE + p0) * DM : nullptr;
    const float* r1 = (p1 >= 0) ? g_eo + ((size_t)e1 * CAPE + p1) * DM : nullptr;
    float* yr = y + (size_t)t * DM;
    for (int d = threadIdx.x * 4; d < DM; d += blockDim.x * 4) {
        float4 a = make_float4(0.f, 0.f, 0.f, 0.f);
        if (r0) {
            float4 v = *reinterpret_cast<const float4*>(r0 + d);
            a.x = fmaf(w0, v.x, a.x); a.y = fmaf(w0, v.y, a.y);
            a.z = fmaf(w0, v.z, a.z); a.w = fmaf(w0, v.w, a.w);
        }
        if (r1) {
            float4 v = *reinterpret_cast<const float4*>(r1 + d);
            a.x = fmaf(w1, v.x, a.x); a.y = fmaf(w1, v.y, a.y);
            a.z = fmaf(w1, v.z, a.z); a.w = fmaf(w1, v.w, a.w);
        }
        *reinterpret_cast<float4*>(yr + d) = a;
    }
}

// ---------------- launch ------------------------------------------------------
extern "C" void kernel_launch(void* const* d_in, const int* in_sizes, int n_in,
                              void* d_out, int out_size)
{
    const float* x    = (const float*)d_in[0];
    const float* wg   = (const float*)d_in[1];
    const float* fc1w = (const float*)d_in[2];
    const float* fc1b = (const float*)d_in[3];
    const float* fc2w = (const float*)d_in[4];
    const float* fc2b = (const float*)d_in[5];
    float* y = (float*)d_out;

    float *disp, *hbuf, *eo;
    cudaGetSymbolAddress((void**)&disp, g_disp);
    cudaGetSymbolAddress((void**)&hbuf, g_h);
    cudaGetSymbolAddress((void**)&eo,   g_eo);

    gate_kernel<<<STOK / 8, 256>>>(x, wg);       // 8 warps/block -> 1 token/warp
    pos_kernel<<<NE, 1024>>>();
    dispatch_kernel<<<STOK * 2, 256>>>(x);

    dim3 g1(HID / 128, CAPE / 128, NE);          // fc1 + gelu
    gemm_kernel<true><<<g1, 256>>>(disp, fc1w, fc1b, hbuf, CAPE, HID, DM);

    dim3 g2(DM / 128, CAPE / 128, NE);           // fc2
    gemm_kernel<false><<<g2, 256>>>(hbuf, fc2w, fc2b, eo, CAPE, DM, HID);

    combine_kernel<<<STOK, 256>>>(y);
}

// round 3
// speedup vs baseline: 1.5447x; 1.5447x over previous
#include <cuda_runtime.h>
#include <cstdint>
#include <math.h>

// Problem constants
#define DM 2048
#define HID 8192
#define NE 8
#define STOK 8192
#define CAPE 2048

// ---------------- scratch (device globals) -----------------------------------
__device__ float g_disp[(size_t)NE * CAPE * DM];
__device__ float g_h[(size_t)NE * CAPE * HID];
__device__ float g_eo[(size_t)NE * CAPE * DM];
__device__ int   g_idx[STOK * 2];
__device__ float g_gate[STOK * 2];
__device__ int   g_pos[STOK * 2];
__device__ float g_gv[STOK * 2];

// ---------------- gate --------------------------------------------------------
__global__ void gate_kernel(const float* __restrict__ x, const float* __restrict__ wg)
{
    int gw = (blockIdx.x * blockDim.x + threadIdx.x) >> 5;
    int lane = threadIdx.x & 31;
    if (gw >= STOK) return;
    const float* xr = x + (size_t)gw * DM;
    float acc[NE];
#pragma unroll
    for (int e = 0; e < NE; e++) acc[e] = 0.f;
    for (int d = lane; d < DM; d += 32) {
        float xv = __ldg(xr + d);
        const float4* w = reinterpret_cast<const float4*>(wg + (size_t)d * NE);
        float4 w0 = __ldg(w), w1 = __ldg(w + 1);
        acc[0] = fmaf(xv, w0.x, acc[0]); acc[1] = fmaf(xv, w0.y, acc[1]);
        acc[2] = fmaf(xv, w0.z, acc[2]); acc[3] = fmaf(xv, w0.w, acc[3]);
        acc[4] = fmaf(xv, w1.x, acc[4]); acc[5] = fmaf(xv, w1.y, acc[5]);
        acc[6] = fmaf(xv, w1.z, acc[6]); acc[7] = fmaf(xv, w1.w, acc[7]);
    }
#pragma unroll
    for (int off = 16; off > 0; off >>= 1)
#pragma unroll
        for (int e = 0; e < NE; e++) acc[e] += __shfl_down_sync(0xffffffffu, acc[e], off);
    if (lane == 0) {
        float mx = acc[0];
#pragma unroll
        for (int e = 1; e < NE; e++) mx = fmaxf(mx, acc[e]);
        float p[NE]; float sum = 0.f;
#pragma unroll
        for (int e = 0; e < NE; e++) { p[e] = expf(acc[e] - mx); sum += p[e]; }
        float inv = 1.f / sum;
#pragma unroll
        for (int e = 0; e < NE; e++) p[e] *= inv;
        int i1 = 0;
#pragma unroll
        for (int e = 1; e < NE; e++) if (p[e] > p[i1]) i1 = e;
        int i2 = (i1 == 0) ? 1 : 0;
#pragma unroll
        for (int e = 0; e < NE; e++) if (e != i1 && p[e] > p[i2]) i2 = e;
        float denom = fmaxf(p[i1] + p[i2], 1e-9f);
        g_idx[gw * 2 + 0] = i1;             g_idx[gw * 2 + 1] = i2;
        g_gate[gw * 2 + 0] = p[i1] / denom; g_gate[gw * 2 + 1] = p[i2] / denom;
    }
}

// ---------------- positions (order-exact per-expert cumsum) -------------------
__global__ void pos_kernel()
{
    int e = blockIdx.x;
    __shared__ int sc[1024];
    int base = 0;
    for (int s = 0; s < 2; ++s) {
        for (int chunk = 0; chunk < STOK; chunk += 1024) {
            int t = chunk + threadIdx.x;
            int m = (g_idx[t * 2 + s] == e) ? 1 : 0;
            sc[threadIdx.x] = m;
            __syncthreads();
            for (int off = 1; off < 1024; off <<= 1) {
                int v = (threadIdx.x >= off) ? sc[threadIdx.x - off] : 0;
                __syncthreads();
                sc[threadIdx.x] += v;
                __syncthreads();
            }
            if (m) {
                int p = base + sc[threadIdx.x] - 1;
                if (p < CAPE) { g_pos[t * 2 + s] = p;  g_gv[t * 2 + s] = g_gate[t * 2 + s]; }
                else          { g_pos[t * 2 + s] = -1; g_gv[t * 2 + s] = 0.f; }
            }
            base += sc[1023];
            __syncthreads();
        }
    }
}

// ---------------- dispatch ----------------------------------------------------
__global__ void dispatch_kernel(const float* __restrict__ x)
{
    int ts = blockIdx.x;
    int t = ts >> 1, s = ts & 1;
    int p = g_pos[t * 2 + s];
    if (p < 0) return;
    int e = g_idx[t * 2 + s];
    const float4* src = reinterpret_cast<const float4*>(x + (size_t)t * DM);
    float4* dst = reinterpret_cast<float4*>(g_disp + ((size_t)e * CAPE + p) * DM);
    for (int i = threadIdx.x; i < DM / 4; i += blockDim.x) dst[i] = src[i];
}

// ---------------- tf32 helpers -------------------------------------------------
__device__ __forceinline__ void splitf(float a, float& hi, float& lo)
{
    uint32_t u;
    asm("cvt.rna.tf32.f32 %0, %1;" : "=r"(u) : "f"(a));
    hi = __uint_as_float(u);
    float l = __fsub_rn(a, hi);
    uint32_t v;
    asm("cvt.rna.tf32.f32 %0, %1;" : "=r"(v) : "f"(l));
    lo = __uint_as_float(v);
}
__device__ __forceinline__ void split4(float4 a, float4& h, float4& l)
{
    splitf(a.x, h.x, l.x); splitf(a.y, h.y, l.y);
    splitf(a.z, h.z, l.z); splitf(a.w, h.w, l.w);
}
__device__ __forceinline__ void mma8(float4& d, const float* a, float b0, float b1)
{
    asm volatile(
        "mma.sync.aligned.m16n8k8.row.col.f32.tf32.tf32.f32 "
        "{%0,%1,%2,%3}, {%4,%5,%6,%7}, {%8,%9}, {%0,%1,%2,%3};"
        : "+f"(d.x), "+f"(d.y), "+f"(d.z), "+f"(d.w)
        : "r"(__float_as_uint(a[0])), "r"(__float_as_uint(a[1])),
          "r"(__float_as_uint(a[2])), "r"(__float_as_uint(a[3])),
          "r"(__float_as_uint(b0)), "r"(__float_as_uint(b1)));
}

// ---------------- tensor GEMM: C[z] = A[z] @ B[z] + bias[z] (opt exact gelu) ---
// A: [M][K] row-major, B: [K][N] row-major (natural weight layout).
// CTA tile 128x128, KC=32, 8 warps (4M x 2N), warp tile 32x64.
// SMEM: Ahi/Alo [128][36], Bhi/Blo [32][136]; stage = 17920 floats, 2 stages.
#define APAD 36
#define BPAD 136
#define AOFF_LO 4608
#define BOFF_HI 9216
#define BOFF_LO 13568
#define SSTR    17920
#define GEMM_SMEM (2 * SSTR * 4)

template <bool GELU>
__global__ void __launch_bounds__(256, 1)
mma_gemm(const float* __restrict__ Ab, const float* __restrict__ Bb,
         const float* __restrict__ biasb, float* __restrict__ Cb,
         int M, int N, int K)
{
    extern __shared__ float sm[];
    int tid = threadIdx.x;
    int lane = tid & 31, wid = tid >> 5;
    int wm = wid & 3, wn = wid >> 2;
    int g = lane >> 2, t4 = lane & 3;

    int z = blockIdx.z;
    const float* A    = Ab    + (size_t)z * M * K;
    const float* B    = Bb    + (size_t)z * K * N;
    const float* bias = biasb + (size_t)z * N;
    float*       C    = Cb    + (size_t)z * M * N;
    int brow = blockIdx.y * 128;
    int bcol = blockIdx.x * 128;

    // fill-thread mapping (per i in 0..3, f = tid + i*256)
    // A: m = f>>3 (0..127), kq = f&7 ;  B: k = f>>5 (0..31), nq = f&31
    int fa_m[4], fa_kq[4], fb_k[4], fb_nq[4];
#pragma unroll
    for (int i = 0; i < 4; i++) {
        int f = tid + i * 256;
        fa_m[i] = f >> 3;  fa_kq[i] = f & 7;
        fb_k[i] = f >> 5;  fb_nq[i] = f & 31;
    }

    float4 acc[2][8];
#pragma unroll
    for (int mi = 0; mi < 2; mi++)
#pragma unroll
        for (int tn = 0; tn < 8; tn++) acc[mi][tn] = make_float4(0.f, 0.f, 0.f, 0.f);

    float4 rA[4], rB[4];

    // ---- prologue: load + store chunk 0 ----
#pragma unroll
    for (int i = 0; i < 4; i++) {
        rA[i] = *reinterpret_cast<const float4*>(A + (size_t)(brow + fa_m[i]) * K + 4 * fa_kq[i]);
        rB[i] = *reinterpret_cast<const float4*>(B + (size_t)fb_k[i] * N + bcol + 4 * fb_nq[i]);
    }
    {
        float* st = sm;
#pragma unroll
        for (int i = 0; i < 4; i++) {
            float4 h, l;
            split4(rA[i], h, l);
            int off = fa_m[i] * APAD + 4 * fa_kq[i];
            *reinterpret_cast<float4*>(st + off) = h;
            *reinterpret_cast<float4*>(st + AOFF_LO + off) = l;
        }
#pragma unroll
        for (int i = 0; i < 4; i++) {
            float4 h, l;
            split4(rB[i], h, l);
            int off = fb_k[i] * BPAD + 4 * fb_nq[i];
            *reinterpret_cast<float4*>(st + BOFF_HI + off) = h;
            *reinterpret_cast<float4*>(st + BOFF_LO + off) = l;
        }
    }
    __syncthreads();

    int nch = K / 32;
    int arow0 = (wm * 32 + g) * APAD;
    int bcol0 = wn * 64 + g;

    for (int c = 0; c < nch; ++c) {
        // prefetch next chunk into registers
        if (c + 1 < nch) {
            int k0 = (c + 1) * 32;
#pragma unroll
            for (int i = 0; i < 4; i++) {
                rA[i] = *reinterpret_cast<const float4*>(A + (size_t)(brow + fa_m[i]) * K + k0 + 4 * fa_kq[i]);
                rB[i] = *reinterpret_cast<const float4*>(B + (size_t)(k0 + fb_k[i]) * N + bcol + 4 * fb_nq[i]);
            }
        }
        // compute on stage c&1
        {
            const float* Ah = sm + (c & 1) * SSTR;
            const float* Al = Ah + AOFF_LO;
            const float* Bh = Ah + BOFF_HI;
            const float* Bl = Ah + BOFF_LO;
#pragma unroll
            for (int ks = 0; ks < 4; ks++) {
                float ah[2][4], al[2][4];
#pragma unroll
                for (int mi = 0; mi < 2; mi++) {
                    int base = arow0 + mi * (16 * APAD) + ks * 8 + t4;
                    ah[mi][0] = Ah[base];
                    ah[mi][1] = Ah[base + 8 * APAD];
                    ah[mi][2] = Ah[base + 4];
                    ah[mi][3] = Ah[base + 8 * APAD + 4];
                    al[mi][0] = Al[base];
                    al[mi][1] = Al[base + 8 * APAD];
                    al[mi][2] = Al[base + 4];
                    al[mi][3] = Al[base + 8 * APAD + 4];
                }
#pragma unroll
                for (int tn = 0; tn < 8; tn++) {
                    int bb = (ks * 8 + t4) * BPAD + bcol0 + tn * 8;
                    float bh0 = Bh[bb], bh1 = Bh[bb + 4 * BPAD];
                    float bl0 = Bl[bb], bl1 = Bl[bb + 4 * BPAD];
#pragma unroll
                    for (int mi = 0; mi < 2; mi++) {
                        mma8(acc[mi][tn], ah[mi], bh0, bh1);   // hi*hi
                        mma8(acc[mi][tn], ah[mi], bl0, bl1);   // hi*lo
                        mma8(acc[mi][tn], al[mi], bh0, bh1);   // lo*hi
                    }
                }
            }
        }
        // store next chunk into the other stage
        if (c + 1 < nch) {
            float* st = sm + ((c + 1) & 1) * SSTR;
#pragma unroll
            for (int i = 0; i < 4; i++) {
                float4 h, l;
                split4(rA[i], h, l);
                int off = fa_m[i] * APAD + 4 * fa_kq[i];
                *reinterpret_cast<float4*>(st + off) = h;
                *reinterpret_cast<float4*>(st + AOFF_LO + off) = l;
            }
#pragma unroll
            for (int i = 0; i < 4; i++) {
                float4 h, l;
                split4(rB[i], h, l);
                int off = fb_k[i] * BPAD + 4 * fb_nq[i];
                *reinterpret_cast<float4*>(st + BOFF_HI + off) = h;
                *reinterpret_cast<float4*>(st + BOFF_LO + off) = l;
            }
            __syncthreads();
        }
    }

    // ---- epilogue: bias (+ exact gelu), direct STG ----
#pragma unroll
    for (int mi = 0; mi < 2; mi++) {
        int row = brow + wm * 32 + mi * 16 + g;
#pragma unroll
        for (int tn = 0; tn < 8; tn++) {
            int col = bcol + wn * 64 + tn * 8 + t4 * 2;
            float2 bv = *reinterpret_cast<const float2*>(bias + col);
            float2 v0, v1;
            v0.x = acc[mi][tn].x + bv.x;  v0.y = acc[mi][tn].y + bv.y;
            v1.x = acc[mi][tn].z + bv.x;  v1.y = acc[mi][tn].w + bv.y;
            if (GELU) {
                v0.x = 0.5f * v0.x * (1.f + erff(v0.x * 0.70710678118654752f));
                v0.y = 0.5f * v0.y * (1.f + erff(v0.y * 0.70710678118654752f));
                v1.x = 0.5f * v1.x * (1.f + erff(v1.x * 0.70710678118654752f));
                v1.y = 0.5f * v1.y * (1.f + erff(v1.y * 0.70710678118654752f));
            }
            *reinterpret_cast<float2*>(C + (size_t)row * N + col) = v0;
            *reinterpret_cast<float2*>(C + (size_t)(row + 8) * N + col) = v1;
        }
    }
}

// ---------------- combine -----------------------------------------------------
__global__ void combine_kernel(float* __restrict__ y)
{
    int t = blockIdx.x;
    int e0 = g_idx[t * 2], e1 = g_idx[t * 2 + 1];
    int p0 = g_pos[t * 2], p1 = g_pos[t * 2 + 1];
    float w0 = g_gv[t * 2], w1 = g_gv[t * 2 + 1];
    const float* r0 = (p0 >= 0) ? g_eo + ((size_t)e0 * CAPE + p0) * DM : nullptr;
    const float* r1 = (p1 >= 0) ? g_eo + ((size_t)e1 * CAPE + p1) * DM : nullptr;
    float* yr = y + (size_t)t * DM;
    for (int d = threadIdx.x * 4; d < DM; d += blockDim.x * 4) {
        float4 a = make_float4(0.f, 0.f, 0.f, 0.f);
        if (r0) {
            float4 v = *reinterpret_cast<const float4*>(r0 + d);
            a.x = fmaf(w0, v.x, a.x); a.y = fmaf(w0, v.y, a.y);
            a.z = fmaf(w0, v.z, a.z); a.w = fmaf(w0, v.w, a.w);
        }
        if (r1) {
            float4 v = *reinterpret_cast<const float4*>(r1 + d);
            a.x = fmaf(w1, v.x, a.x); a.y = fmaf(w1, v.y, a.y);
            a.z = fmaf(w1, v.z, a.z); a.w = fmaf(w1, v.w, a.w);
        }
        *reinterpret_cast<float4*>(yr + d) = a;
    }
}

// ---------------- launch ------------------------------------------------------
extern "C" void kernel_launch(void* const* d_in, const int* in_sizes, int n_in,
                              void* d_out, int out_size)
{
    const float* x    = (const float*)d_in[0];
    const float* wg   = (const float*)d_in[1];
    const float* fc1w = (const float*)d_in[2];
    const float* fc1b = (const float*)d_in[3];
    const float* fc2w = (const float*)d_in[4];
    const float* fc2b = (const float*)d_in[5];
    float* y = (float*)d_out;

    float *disp, *hbuf, *eo;
    cudaGetSymbolAddress((void**)&disp, g_disp);
    cudaGetSymbolAddress((void**)&hbuf, g_h);
    cudaGetSymbolAddress((void**)&eo,   g_eo);

    cudaFuncSetAttribute(mma_gemm<true>,  cudaFuncAttributeMaxDynamicSharedMemorySize, GEMM_SMEM);
    cudaFuncSetAttribute(mma_gemm<false>, cudaFuncAttributeMaxDynamicSharedMemorySize, GEMM_SMEM);

    gate_kernel<<<STOK / 8, 256>>>(x, wg);
    pos_kernel<<<NE, 1024>>>();
    dispatch_kernel<<<STOK * 2, 256>>>(x);

    dim3 g1(HID / 128, CAPE / 128, NE);   // fc1 + gelu: [CAPE x DM] @ [DM x HID]
    mma_gemm<true><<<g1, 256, GEMM_SMEM>>>(disp, fc1w, fc1b, hbuf, CAPE, HID, DM);

    dim3 g2(DM / 128, CAPE / 128, NE);    // fc2: [CAPE x HID] @ [HID x DM]
    mma_gemm<false><<<g2, 256, GEMM_SMEM>>>(hbuf, fc2w, fc2b, eo, CAPE, DM, HID);

    combine_kernel<<<STOK, 256>>>(y);
}

// round 4
// speedup vs baseline: 2.5820x; 1.6715x over previous
#include <cuda_runtime.h>
#include <cuda_bf16.h>
#include <cstdint>
#include <math.h>

#define DM 2048
#define HID 8192
#define NE 8
#define STOK 8192
#define CAPE 2048

// ---------------- scratch (device globals, zero-init) --------------------------
__device__ unsigned g_disp_hi[(size_t)NE * CAPE * DM / 2];
__device__ unsigned g_disp_lo[(size_t)NE * CAPE * DM / 2];
__device__ unsigned g_h_hi[(size_t)NE * CAPE * HID / 2];
__device__ unsigned g_h_lo[(size_t)NE * CAPE * HID / 2];
__device__ unsigned g_w1hi[(size_t)NE * (DM / 2) * HID];
__device__ unsigned g_w1lo[(size_t)NE * (DM / 2) * HID];
__device__ unsigned g_w2hi[(size_t)NE * (HID / 2) * DM];
__device__ unsigned g_w2lo[(size_t)NE * (HID / 2) * DM];
__device__ float    g_eo[(size_t)NE * CAPE * DM];
__device__ int      g_idx[STOK * 2];
__device__ float    g_gate[STOK * 2];
__device__ int      g_pos[STOK * 2];
__device__ float    g_gv[STOK * 2];

// ---------------- helpers -------------------------------------------------------
__device__ __forceinline__ uint32_t smem_u32(const void* p) {
    uint32_t a;
    asm("{ .reg .u64 t; cvta.to.shared.u64 t, %1; cvt.u32.u64 %0, t; }" : "=r"(a) : "l"(p));
    return a;
}
__device__ __forceinline__ void cp16(uint32_t dst, const void* src) {
    asm volatile("cp.async.cg.shared.global [%0], [%1], 16;" :: "r"(dst), "l"(src) : "memory");
}
// pack k-pair (even e, odd o) into bf16x2 hi word + residual lo word; low16 = even
__device__ __forceinline__ void packsplit2(float e, float o, unsigned& hi, unsigned& lo) {
    __nv_bfloat162 h2, l2;
    h2.x = __float2bfloat16_rn(e);
    h2.y = __float2bfloat16_rn(o);
    l2.x = __float2bfloat16_rn(e - __bfloat162float(h2.x));
    l2.y = __float2bfloat16_rn(o - __bfloat162float(h2.y));
    hi = *reinterpret_cast<unsigned*>(&h2);
    lo = *reinterpret_cast<unsigned*>(&l2);
}
__device__ __forceinline__ void mma16(float4& d, const unsigned* a, unsigned b0, unsigned b1) {
    asm volatile(
        "mma.sync.aligned.m16n8k16.row.col.f32.bf16.bf16.f32 "
        "{%0,%1,%2,%3}, {%4,%5,%6,%7}, {%8,%9}, {%0,%1,%2,%3};"
        : "+f"(d.x), "+f"(d.y), "+f"(d.z), "+f"(d.w)
        : "r"(a[0]), "r"(a[1]), "r"(a[2]), "r"(a[3]), "r"(b0), "r"(b1));
}

// ---------------- gate ----------------------------------------------------------
__global__ void gate_kernel(const float* __restrict__ x, const float* __restrict__ wg)
{
    int gw = (blockIdx.x * blockDim.x + threadIdx.x) >> 5;
    int lane = threadIdx.x & 31;
    if (gw >= STOK) return;
    const float* xr = x + (size_t)gw * DM;
    float acc[NE];
#pragma unroll
    for (int e = 0; e < NE; e++) acc[e] = 0.f;
    for (int d = lane; d < DM; d += 32) {
        float xv = __ldg(xr + d);
        const float4* w = reinterpret_cast<const float4*>(wg + (size_t)d * NE);
        float4 w0 = __ldg(w), w1 = __ldg(w + 1);
        acc[0] = fmaf(xv, w0.x, acc[0]); acc[1] = fmaf(xv, w0.y, acc[1]);
        acc[2] = fmaf(xv, w0.z, acc[2]); acc[3] = fmaf(xv, w0.w, acc[3]);
        acc[4] = fmaf(xv, w1.x, acc[4]); acc[5] = fmaf(xv, w1.y, acc[5]);
        acc[6] = fmaf(xv, w1.z, acc[6]); acc[7] = fmaf(xv, w1.w, acc[7]);
    }
#pragma unroll
    for (int off = 16; off > 0; off >>= 1)
#pragma unroll
        for (int e = 0; e < NE; e++) acc[e] += __shfl_down_sync(0xffffffffu, acc[e], off);
    if (lane == 0) {
        float mx = acc[0];
#pragma unroll
        for (int e = 1; e < NE; e++) mx = fmaxf(mx, acc[e]);
        float p[NE]; float sum = 0.f;
#pragma unroll
        for (int e = 0; e < NE; e++) { p[e] = expf(acc[e] - mx); sum += p[e]; }
        float inv = 1.f / sum;
#pragma unroll
        for (int e = 0; e < NE; e++) p[e] *= inv;
        int i1 = 0;
#pragma unroll
        for (int e = 1; e < NE; e++) if (p[e] > p[i1]) i1 = e;
        int i2 = (i1 == 0) ? 1 : 0;
#pragma unroll
        for (int e = 0; e < NE; e++) if (e != i1 && p[e] > p[i2]) i2 = e;
        float denom = fmaxf(p[i1] + p[i2], 1e-9f);
        g_idx[gw * 2 + 0] = i1;             g_idx[gw * 2 + 1] = i2;
        g_gate[gw * 2 + 0] = p[i1] / denom; g_gate[gw * 2 + 1] = p[i2] / denom;
    }
}

// ---------------- positions -----------------------------------------------------
__global__ void pos_kernel()
{
    int e = blockIdx.x;
    __shared__ int sc[1024];
    int base = 0;
    for (int s = 0; s < 2; ++s) {
        for (int chunk = 0; chunk < STOK; chunk += 1024) {
            int t = chunk + threadIdx.x;
            int m = (g_idx[t * 2 + s] == e) ? 1 : 0;
            sc[threadIdx.x] = m;
            __syncthreads();
            for (int off = 1; off < 1024; off <<= 1) {
                int v = (threadIdx.x >= off) ? sc[threadIdx.x - off] : 0;
                __syncthreads();
                sc[threadIdx.x] += v;
                __syncthreads();
            }
            if (m) {
                int p = base + sc[threadIdx.x] - 1;
                if (p < CAPE) { g_pos[t * 2 + s] = p;  g_gv[t * 2 + s] = g_gate[t * 2 + s]; }
                else          { g_pos[t * 2 + s] = -1; g_gv[t * 2 + s] = 0.f; }
            }
            base += sc[1023];
            __syncthreads();
        }
    }
}

// ---------------- dispatch: scatter x rows as packed bf16 hi/lo planes ----------
__global__ void dispatch_kernel(const float* __restrict__ x)
{
    int ts = blockIdx.x;
    int t = ts >> 1, s = ts & 1;
    int p = g_pos[t * 2 + s];
    if (p < 0) return;
    int e = g_idx[t * 2 + s];
    const float4* src = reinterpret_cast<const float4*>(x + (size_t)t * DM);
    size_t ro = ((size_t)e * CAPE + p) * (DM / 2);
    uint4* dhi = reinterpret_cast<uint4*>(g_disp_hi + ro);
    uint4* dlo = reinterpret_cast<uint4*>(g_disp_lo + ro);
    int j = threadIdx.x;                 // 256 threads, 256 uint4 = DM/2 u32
    float4 a = src[j * 2], b = src[j * 2 + 1];
    uint4 h, l;
    packsplit2(a.x, a.y, h.x, l.x);
    packsplit2(a.z, a.w, h.y, l.y);
    packsplit2(b.x, b.y, h.z, l.z);
    packsplit2(b.z, b.w, h.w, l.w);
    dhi[j] = h; dlo[j] = l;
}

// ---------------- weight pack: [E][K][N] fp32 -> hi/lo u32 planes [E][K/2][N] ---
__global__ void packw_kernel(const float* __restrict__ w, unsigned* __restrict__ whi,
                             unsigned* __restrict__ wlo, int K, int N)
{
    size_t idx = (size_t)blockIdx.x * 256 + threadIdx.x;
    int n4 = N / 4;
    size_t items = (size_t)NE * (K / 2) * n4;
    if (idx >= items) return;
    int nq = (int)(idx % n4);
    size_t r = idx / n4;
    int k2 = (int)(r % (K / 2));
    int e = (int)(r / (K / 2));
    const float* base = w + ((size_t)e * K + 2 * k2) * N + nq * 4;
    float4 r0 = *reinterpret_cast<const float4*>(base);
    float4 r1 = *reinterpret_cast<const float4*>(base + N);
    uint4 h, l;
    packsplit2(r0.x, r1.x, h.x, l.x);
    packsplit2(r0.y, r1.y, h.y, l.y);
    packsplit2(r0.z, r1.z, h.z, l.z);
    packsplit2(r0.w, r1.w, h.w, l.w);
    size_t o = ((size_t)e * (K / 2) + k2) * N + nq * 4;
    *reinterpret_cast<uint4*>(whi + o) = h;
    *reinterpret_cast<uint4*>(wlo + o) = l;
}

// ---------------- bf16x3 tensor GEMM --------------------------------------------
// A planes [M][K2] u32, B planes [K2][N] u32 (k-pairs bf16x2), 128x128 tile,
// KC=16 u32 (32 k), 4-stage cp.async pipeline, 8 warps (4m x 2n), warp 32x64.
#define K2C 16
#define A_STRIDE 20
#define B_STRIDE 136
#define OFF_ALO 2560
#define OFF_BHI 5120
#define OFF_BLO 7296
#define SS 9472
#define NSTAGE 4
#define GEMM_SMEM (NSTAGE * SS * 4)

template <bool PACK>
__global__ void __launch_bounds__(256, 1)
mma_gemm(const unsigned* __restrict__ Ahi_, const unsigned* __restrict__ Alo_,
         const unsigned* __restrict__ Bhi_, const unsigned* __restrict__ Blo_,
         const float* __restrict__ biasb, float* __restrict__ Cf,
         unsigned* __restrict__ Ohi, unsigned* __restrict__ Olo,
         int M, int N, int K2)
{
    extern __shared__ unsigned sm[];
    uint32_t smem_base = smem_u32(sm);
    int tid = threadIdx.x;
    int lane = tid & 31, wid = tid >> 5;
    int wm = wid & 3, wn = wid >> 2;
    int g = lane >> 2, t4 = lane & 3;

    int z = blockIdx.z;
    const unsigned* Ahi = Ahi_ + (size_t)z * M * K2;
    const unsigned* Alo = Alo_ + (size_t)z * M * K2;
    const unsigned* Bhi = Bhi_ + (size_t)z * K2 * N;
    const unsigned* Blo = Blo_ + (size_t)z * K2 * N;
    const float* bias = biasb + (size_t)z * N;
    int brow = blockIdx.y * 128;
    int bcol = blockIdx.x * 128;

    float4 acc[2][8];
#pragma unroll
    for (int mi = 0; mi < 2; mi++)
#pragma unroll
        for (int tn = 0; tn < 8; tn++) acc[mi][tn] = make_float4(0.f, 0.f, 0.f, 0.f);

    auto fill = [&](int st, int cc) {
        uint32_t base = smem_base + (uint32_t)st * (SS * 4);
#pragma unroll
        for (int i = 0; i < 2; i++) {
            int f = tid + i * 256;
            int row = f >> 2, q = f & 3;
            size_t so = (size_t)(brow + row) * K2 + cc * K2C + q * 4;
            uint32_t d = base + (uint32_t)(row * A_STRIDE + q * 4) * 4;
            cp16(d, Ahi + so);
            cp16(d + OFF_ALO * 4, Alo + so);
        }
#pragma unroll
        for (int i = 0; i < 2; i++) {
            int f = tid + i * 256;
            int row = f >> 5, q = f & 31;
            size_t so = (size_t)(cc * K2C + row) * N + bcol + q * 4;
            uint32_t d = base + (uint32_t)(OFF_BHI + row * B_STRIDE + q * 4) * 4;
            cp16(d, Bhi + so);
            cp16(d + (OFF_BLO - OFF_BHI) * 4, Blo + so);
        }
        asm volatile("cp.async.commit_group;" ::: "memory");
    };

    int nch = K2 / K2C;
    fill(0, 0); fill(1, 1); fill(2, 2);

    for (int c = 0; c < nch; ++c) {
        asm volatile("cp.async.wait_group 2;" ::: "memory");
        __syncthreads();
        if (c + 3 < nch) fill((c + 3) & 3, c + 3);

        const unsigned* S  = sm + (size_t)(c & 3) * SS;
        const unsigned* Ah = S;
        const unsigned* Al = S + OFF_ALO;
        const unsigned* Bh = S + OFF_BHI;
        const unsigned* Bl = S + OFF_BLO;
#pragma unroll
        for (int ks = 0; ks < 2; ks++) {
            unsigned ah[2][4], al[2][4];
#pragma unroll
            for (int mi = 0; mi < 2; mi++) {
                int r0 = (wm * 32 + mi * 16 + g) * A_STRIDE + ks * 8 + t4;
                ah[mi][0] = Ah[r0];
                ah[mi][1] = Ah[r0 + 8 * A_STRIDE];
                ah[mi][2] = Ah[r0 + 4];
                ah[mi][3] = Ah[r0 + 8 * A_STRIDE + 4];
                al[mi][0] = Al[r0];
                al[mi][1] = Al[r0 + 8 * A_STRIDE];
                al[mi][2] = Al[r0 + 4];
                al[mi][3] = Al[r0 + 8 * A_STRIDE + 4];
            }
#pragma unroll
            for (int tn = 0; tn < 8; tn++) {
                int bb = (ks * 8 + t4) * B_STRIDE + wn * 64 + tn * 8 + g;
                unsigned bh0 = Bh[bb], bh1 = Bh[bb + 4 * B_STRIDE];
                unsigned bl0 = Bl[bb], bl1 = Bl[bb + 4 * B_STRIDE];
#pragma unroll
                for (int mi = 0; mi < 2; mi++) {
                    mma16(acc[mi][tn], ah[mi], bh0, bh1);   // hi*hi
                    mma16(acc[mi][tn], ah[mi], bl0, bl1);   // hi*lo
                    mma16(acc[mi][tn], al[mi], bh0, bh1);   // lo*hi
                }
            }
        }
    }

    // ---- epilogue ----
    if (PACK) {
        unsigned* ohi = Ohi + (size_t)z * M * (N / 2);
        unsigned* olo = Olo + (size_t)z * M * (N / 2);
#pragma unroll
        for (int mi = 0; mi < 2; mi++) {
            int row = brow + wm * 32 + mi * 16 + g;
#pragma unroll
            for (int tn = 0; tn < 8; tn++) {
                int col = bcol + wn * 64 + tn * 8 + t4 * 2;
                float2 bv = *reinterpret_cast<const float2*>(bias + col);
                float v0 = acc[mi][tn].x + bv.x, v1 = acc[mi][tn].y + bv.y;
                float v2 = acc[mi][tn].z + bv.x, v3 = acc[mi][tn].w + bv.y;
                v0 = 0.5f * v0 * (1.f + erff(v0 * 0.70710678118654752f));
                v1 = 0.5f * v1 * (1.f + erff(v1 * 0.70710678118654752f));
                v2 = 0.5f * v2 * (1.f + erff(v2 * 0.70710678118654752f));
                v3 = 0.5f * v3 * (1.f + erff(v3 * 0.70710678118654752f));
                int col2 = col >> 1;
                unsigned h, l;
                packsplit2(v0, v1, h, l);
                ohi[(size_t)row * (N / 2) + col2] = h;
                olo[(size_t)row * (N / 2) + col2] = l;
                packsplit2(v2, v3, h, l);
                ohi[(size_t)(row + 8) * (N / 2) + col2] = h;
                olo[(size_t)(row + 8) * (N / 2) + col2] = l;
            }
        }
    } else {
        float* C = Cf + (size_t)z * M * N;
#pragma unroll
        for (int mi = 0; mi < 2; mi++) {
            int row = brow + wm * 32 + mi * 16 + g;
#pragma unroll
            for (int tn = 0; tn < 8; tn++) {
                int col = bcol + wn * 64 + tn * 8 + t4 * 2;
                float2 bv = *reinterpret_cast<const float2*>(bias + col);
                float2 v0, v1;
                v0.x = acc[mi][tn].x + bv.x;  v0.y = acc[mi][tn].y + bv.y;
                v1.x = acc[mi][tn].z + bv.x;  v1.y = acc[mi][tn].w + bv.y;
                *reinterpret_cast<float2*>(C + (size_t)row * N + col) = v0;
                *reinterpret_cast<float2*>(C + (size_t)(row + 8) * N + col) = v1;
            }
        }
    }
}

// ---------------- combine -------------------------------------------------------
__global__ void combine_kernel(float* __restrict__ y)
{
    int t = blockIdx.x;
    int e0 = g_idx[t * 2], e1 = g_idx[t * 2 + 1];
    int p0 = g_pos[t * 2], p1 = g_pos[t * 2 + 1];
    float w0 = g_gv[t * 2], w1 = g_gv[t * 2 + 1];
    const float* r0 = (p0 >= 0) ? g_eo + ((size_t)e0 * CAPE + p0) * DM : nullptr;
    const float* r1 = (p1 >= 0) ? g_eo + ((size_t)e1 * CAPE + p1) * DM : nullptr;
    float* yr = y + (size_t)t * DM;
    for (int d = threadIdx.x * 4; d < DM; d += blockDim.x * 4) {
        float4 a = make_float4(0.f, 0.f, 0.f, 0.f);
        if (r0) {
            float4 v = *reinterpret_cast<const float4*>(r0 + d);
            a.x = fmaf(w0, v.x, a.x); a.y = fmaf(w0, v.y, a.y);
            a.z = fmaf(w0, v.z, a.z); a.w = fmaf(w0, v.w, a.w);
        }
        if (r1) {
            float4 v = *reinterpret_cast<const float4*>(r1 + d);
            a.x = fmaf(w1, v.x, a.x); a.y = fmaf(w1, v.y, a.y);
            a.z = fmaf(w1, v.z, a.z); a.w = fmaf(w1, v.w, a.w);
        }
        *reinterpret_cast<float4*>(yr + d) = a;
    }
}

// ---------------- launch ---------------------------------------------------------
extern "C" void kernel_launch(void* const* d_in, const int* in_sizes, int n_in,
                              void* d_out, int out_size)
{
    const float* x    = (const float*)d_in[0];
    const float* wg   = (const float*)d_in[1];
    const float* fc1w = (const float*)d_in[2];
    const float* fc1b = (const float*)d_in[3];
    const float* fc2w = (const float*)d_in[4];
    const float* fc2b = (const float*)d_in[5];
    float* y = (float*)d_out;

    unsigned *dhi, *dlo, *hhi, *hlo, *w1h, *w1l, *w2h, *w2l;
    float* eo;
    cudaGetSymbolAddress((void**)&dhi, g_disp_hi);
    cudaGetSymbolAddress((void**)&dlo, g_disp_lo);
    cudaGetSymbolAddress((void**)&hhi, g_h_hi);
    cudaGetSymbolAddress((void**)&hlo, g_h_lo);
    cudaGetSymbolAddress((void**)&w1h, g_w1hi);
    cudaGetSymbolAddress((void**)&w1l, g_w1lo);
    cudaGetSymbolAddress((void**)&w2h, g_w2hi);
    cudaGetSymbolAddress((void**)&w2l, g_w2lo);
    cudaGetSymbolAddress((void**)&eo,  g_eo);

    cudaFuncSetAttribute(mma_gemm<true>,  cudaFuncAttributeMaxDynamicSharedMemorySize, GEMM_SMEM);
    cudaFuncSetAttribute(mma_gemm<false>, cudaFuncAttributeMaxDynamicSharedMemorySize, GEMM_SMEM);

    // weight packing (hi/lo bf16 planes)
    packw_kernel<<<65536, 256>>>(fc1w, w1h, w1l, DM, HID);
    packw_kernel<<<65536, 256>>>(fc2w, w2h, w2l, HID, DM);

    gate_kernel<<<STOK / 8, 256>>>(x, wg);
    pos_kernel<<<NE, 1024>>>();
    dispatch_kernel<<<STOK * 2, 256>>>(x);

    dim3 g1(HID / 128, CAPE / 128, NE);   // fc1 + gelu -> packed h
    mma_gemm<true><<<g1, 256, GEMM_SMEM>>>(dhi, dlo, w1h, w1l, fc1b,
                                           nullptr, hhi, hlo, CAPE, HID, DM / 2);

    dim3 g2(DM / 128, CAPE / 128, NE);    // fc2 -> fp32 eo
    mma_gemm<false><<<g2, 256, GEMM_SMEM>>>(hhi, hlo, w2h, w2l, fc2b,
                                            eo, nullptr, nullptr, CAPE, DM, HID / 2);

    combine_kernel<<<STOK, 256>>>(y);
}

// round 6
// speedup vs baseline: 2.5867x; 1.0018x over previous
#include <cuda_runtime.h>
#include <cuda_bf16.h>
#include <cstdint>
#include <math.h>

#define DM 2048
#define HID 8192
#define NE 8
#define STOK 8192
#define CAPE 2048

// ---------------- scratch (device globals, zero-init) --------------------------
__device__ unsigned g_disp_hi[(size_t)NE * CAPE * DM / 2];
__device__ unsigned g_disp_lo[(size_t)NE * CAPE * DM / 2];
__device__ unsigned g_h_hi[(size_t)NE * CAPE * HID / 2];
__device__ unsigned g_h_lo[(size_t)NE * CAPE * HID / 2];
__device__ unsigned g_w1hi[(size_t)NE * (DM / 2) * HID];
__device__ unsigned g_w1lo[(size_t)NE * (DM / 2) * HID];
__device__ unsigned g_w2hi[(size_t)NE * (HID / 2) * DM];
__device__ unsigned g_w2lo[(size_t)NE * (HID / 2) * DM];
__device__ float    g_eo[(size_t)NE * CAPE * DM];
__device__ int      g_idx[STOK * 2];
__device__ float    g_gate[STOK * 2];
__device__ int      g_pos[STOK * 2];
__device__ float    g_gv[STOK * 2];

// ---------------- helpers -------------------------------------------------------
__device__ __forceinline__ uint32_t smem_u32(const void* p) {
    uint32_t a;
    asm("{ .reg .u64 t; cvta.to.shared.u64 t, %1; cvt.u32.u64 %0, t; }" : "=r"(a) : "l"(p));
    return a;
}
__device__ __forceinline__ void cp16(uint32_t dst, const void* src) {
    asm volatile("cp.async.cg.shared.global [%0], [%1], 16;" :: "r"(dst), "l"(src) : "memory");
}
// pack k-pair (even e, odd o) into bf16x2 hi word + residual lo word; low16 = even
__device__ __forceinline__ void packsplit2(float e, float o, unsigned& hi, unsigned& lo) {
    __nv_bfloat162 h2, l2;
    h2.x = __float2bfloat16_rn(e);
    h2.y = __float2bfloat16_rn(o);
    l2.x = __float2bfloat16_rn(e - __bfloat162float(h2.x));
    l2.y = __float2bfloat16_rn(o - __bfloat162float(h2.y));
    hi = *reinterpret_cast<unsigned*>(&h2);
    lo = *reinterpret_cast<unsigned*>(&l2);
}
__device__ __forceinline__ void mma16(float4& d, const unsigned* a, unsigned b0, unsigned b1) {
    asm volatile(
        "mma.sync.aligned.m16n8k16.row.col.f32.bf16.bf16.f32 "
        "{%0,%1,%2,%3}, {%4,%5,%6,%7}, {%8,%9}, {%0,%1,%2,%3};"
        : "+f"(d.x), "+f"(d.y), "+f"(d.z), "+f"(d.w)
        : "r"(a[0]), "r"(a[1]), "r"(a[2]), "r"(a[3]), "r"(b0), "r"(b1));
}

// ---------------- gate ----------------------------------------------------------
__global__ void gate_kernel(const float* __restrict__ x, const float* __restrict__ wg)
{
    int gw = (blockIdx.x * blockDim.x + threadIdx.x) >> 5;
    int lane = threadIdx.x & 31;
    if (gw >= STOK) return;
    const float* xr = x + (size_t)gw * DM;
    float acc[NE];
#pragma unroll
    for (int e = 0; e < NE; e++) acc[e] = 0.f;
    for (int d = lane; d < DM; d += 32) {
        float xv = __ldg(xr + d);
        const float4* w = reinterpret_cast<const float4*>(wg + (size_t)d * NE);
        float4 w0 = __ldg(w), w1 = __ldg(w + 1);
        acc[0] = fmaf(xv, w0.x, acc[0]); acc[1] = fmaf(xv, w0.y, acc[1]);
        acc[2] = fmaf(xv, w0.z, acc[2]); acc[3] = fmaf(xv, w0.w, acc[3]);
        acc[4] = fmaf(xv, w1.x, acc[4]); acc[5] = fmaf(xv, w1.y, acc[5]);
        acc[6] = fmaf(xv, w1.z, acc[6]); acc[7] = fmaf(xv, w1.w, acc[7]);
    }
#pragma unroll
    for (int off = 16; off > 0; off >>= 1)
#pragma unroll
        for (int e = 0; e < NE; e++) acc[e] += __shfl_down_sync(0xffffffffu, acc[e], off);
    if (lane == 0) {
        float mx = acc[0];
#pragma unroll
        for (int e = 1; e < NE; e++) mx = fmaxf(mx, acc[e]);
        float p[NE]; float sum = 0.f;
#pragma unroll
        for (int e = 0; e < NE; e++) { p[e] = expf(acc[e] - mx); sum += p[e]; }
        float inv = 1.f / sum;
#pragma unroll
        for (int e = 0; e < NE; e++) p[e] *= inv;
        int i1 = 0;
#pragma unroll
        for (int e = 1; e < NE; e++) if (p[e] > p[i1]) i1 = e;
        int i2 = (i1 == 0) ? 1 : 0;
#pragma unroll
        for (int e = 0; e < NE; e++) if (e != i1 && p[e] > p[i2]) i2 = e;
        float denom = fmaxf(p[i1] + p[i2], 1e-9f);
        g_idx[gw * 2 + 0] = i1;             g_idx[gw * 2 + 1] = i2;
        g_gate[gw * 2 + 0] = p[i1] / denom; g_gate[gw * 2 + 1] = p[i2] / denom;
    }
}

// ---------------- positions -----------------------------------------------------
__global__ void pos_kernel()
{
    int e = blockIdx.x;
    __shared__ int sc[1024];
    int base = 0;
    for (int s = 0; s < 2; ++s) {
        for (int chunk = 0; chunk < STOK; chunk += 1024) {
            int t = chunk + threadIdx.x;
            int m = (g_idx[t * 2 + s] == e) ? 1 : 0;
            sc[threadIdx.x] = m;
            __syncthreads();
            for (int off = 1; off < 1024; off <<= 1) {
                int v = (threadIdx.x >= off) ? sc[threadIdx.x - off] : 0;
                __syncthreads();
                sc[threadIdx.x] += v;
                __syncthreads();
            }
            if (m) {
                int p = base + sc[threadIdx.x] - 1;
                if (p < CAPE) { g_pos[t * 2 + s] = p;  g_gv[t * 2 + s] = g_gate[t * 2 + s]; }
                else          { g_pos[t * 2 + s] = -1; g_gv[t * 2 + s] = 0.f; }
            }
            base += sc[1023];
            __syncthreads();
        }
    }
}

// ---------------- dispatch: scatter x rows as packed bf16 hi/lo planes ----------
__global__ void dispatch_kernel(const float* __restrict__ x)
{
    int ts = blockIdx.x;
    int t = ts >> 1, s = ts & 1;
    int p = g_pos[t * 2 + s];
    if (p < 0) return;
    int e = g_idx[t * 2 + s];
    const float4* src = reinterpret_cast<const float4*>(x + (size_t)t * DM);
    size_t ro = ((size_t)e * CAPE + p) * (DM / 2);
    uint4* dhi = reinterpret_cast<uint4*>(g_disp_hi + ro);
    uint4* dlo = reinterpret_cast<uint4*>(g_disp_lo + ro);
    int j = threadIdx.x;                 // 256 threads, 256 uint4 = DM/2 u32
    float4 a = src[j * 2], b = src[j * 2 + 1];
    uint4 h, l;
    packsplit2(a.x, a.y, h.x, l.x);
    packsplit2(a.z, a.w, h.y, l.y);
    packsplit2(b.x, b.y, h.z, l.z);
    packsplit2(b.z, b.w, h.w, l.w);
    dhi[j] = h; dlo[j] = l;
}

// ---------------- weight pack: [E][K][N] fp32 -> hi/lo u32 planes [E][K/2][N] ---
__global__ void packw_kernel(const float* __restrict__ w, unsigned* __restrict__ whi,
                             unsigned* __restrict__ wlo, int K, int N)
{
    size_t idx = (size_t)blockIdx.x * 256 + threadIdx.x;
    int n4 = N / 4;
    size_t items = (size_t)NE * (K / 2) * n4;
    if (idx >= items) return;
    int nq = (int)(idx % n4);
    size_t r = idx / n4;
    int k2 = (int)(r % (K / 2));
    int e = (int)(r / (K / 2));
    const float* base = w + ((size_t)e * K + 2 * k2) * N + nq * 4;
    float4 r0 = *reinterpret_cast<const float4*>(base);
    float4 r1 = *reinterpret_cast<const float4*>(base + N);
    uint4 h, l;
    packsplit2(r0.x, r1.x, h.x, l.x);
    packsplit2(r0.y, r1.y, h.y, l.y);
    packsplit2(r0.z, r1.z, h.z, l.z);
    packsplit2(r0.w, r1.w, h.w, l.w);
    size_t o = ((size_t)e * (K / 2) + k2) * N + nq * 4;
    *reinterpret_cast<uint4*>(whi + o) = h;
    *reinterpret_cast<uint4*>(wlo + o) = l;
}

// ---------------- bf16x3 tensor GEMM --------------------------------------------
// A planes [M][K2] u32, B planes [K2][N] u32 (k-pairs bf16x2), 128x128 tile,
// KC=16 u32 (32 k), 4-stage cp.async pipeline, 8 warps (4m x 2n), warp 32x64.
#define K2C 16
#define A_STRIDE 20
#define B_STRIDE 136
#define OFF_ALO 2560
#define OFF_BHI 5120
#define OFF_BLO 7296
#define SS 9472
#define NSTAGE 4
#define GEMM_SMEM (NSTAGE * SS * 4)

template <bool PACK>
__global__ void __launch_bounds__(256, 1)
mma_gemm(const unsigned* __restrict__ Ahi_, const unsigned* __restrict__ Alo_,
         const unsigned* __restrict__ Bhi_, const unsigned* __restrict__ Blo_,
         const float* __restrict__ biasb, float* __restrict__ Cf,
         unsigned* __restrict__ Ohi, unsigned* __restrict__ Olo,
         int M, int N, int K2)
{
    extern __shared__ unsigned sm[];
    uint32_t smem_base = smem_u32(sm);
    int tid = threadIdx.x;
    int lane = tid & 31, wid = tid >> 5;
    int wm = wid & 3, wn = wid >> 2;
    int g = lane >> 2, t4 = lane & 3;

    int z = blockIdx.z;
    const unsigned* Ahi = Ahi_ + (size_t)z * M * K2;
    const unsigned* Alo = Alo_ + (size_t)z * M * K2;
    const unsigned* Bhi = Bhi_ + (size_t)z * K2 * N;
    const unsigned* Blo = Blo_ + (size_t)z * K2 * N;
    const float* bias = biasb + (size_t)z * N;
    int brow = blockIdx.y * 128;
    int bcol = blockIdx.x * 128;

    float4 acc[2][8];
#pragma unroll
    for (int mi = 0; mi < 2; mi++)
#pragma unroll
        for (int tn = 0; tn < 8; tn++) acc[mi][tn] = make_float4(0.f, 0.f, 0.f, 0.f);

    auto fill = [&](int st, int cc) {
        uint32_t base = smem_base + (uint32_t)st * (SS * 4);
#pragma unroll
        for (int i = 0; i < 2; i++) {
            int f = tid + i * 256;
            int row = f >> 2, q = f & 3;
            size_t so = (size_t)(brow + row) * K2 + cc * K2C + q * 4;
            uint32_t d = base + (uint32_t)(row * A_STRIDE + q * 4) * 4;
            cp16(d, Ahi + so);
            cp16(d + OFF_ALO * 4, Alo + so);
        }
#pragma unroll
        for (int i = 0; i < 2; i++) {
            int f = tid + i * 256;
            int row = f >> 5, q = f & 31;
            size_t so = (size_t)(cc * K2C + row) * N + bcol + q * 4;
            uint32_t d = base + (uint32_t)(OFF_BHI + row * B_STRIDE + q * 4) * 4;
            cp16(d, Bhi + so);
            cp16(d + (OFF_BLO - OFF_BHI) * 4, Blo + so);
        }
        asm volatile("cp.async.commit_group;" ::: "memory");
    };

    int nch = K2 / K2C;
    fill(0, 0); fill(1, 1); fill(2, 2);

    for (int c = 0; c < nch; ++c) {
        asm volatile("cp.async.wait_group 2;" ::: "memory");
        __syncthreads();
        if (c + 3 < nch) fill((c + 3) & 3, c + 3);

        const unsigned* S  = sm + (size_t)(c & 3) * SS;
        const unsigned* Ah = S;
        const unsigned* Al = S + OFF_ALO;
        const unsigned* Bh = S + OFF_BHI;
        const unsigned* Bl = S + OFF_BLO;
#pragma unroll
        for (int ks = 0; ks < 2; ks++) {
            unsigned ah[2][4], al[2][4];
#pragma unroll
            for (int mi = 0; mi < 2; mi++) {
                int r0 = (wm * 32 + mi * 16 + g) * A_STRIDE + ks * 8 + t4;
                ah[mi][0] = Ah[r0];
                ah[mi][1] = Ah[r0 + 8 * A_STRIDE];
                ah[mi][2] = Ah[r0 + 4];
                ah[mi][3] = Ah[r0 + 8 * A_STRIDE + 4];
                al[mi][0] = Al[r0];
                al[mi][1] = Al[r0 + 8 * A_STRIDE];
                al[mi][2] = Al[r0 + 4];
                al[mi][3] = Al[r0 + 8 * A_STRIDE + 4];
            }
#pragma unroll
            for (int tn = 0; tn < 8; tn++) {
                int bb = (ks * 8 + t4) * B_STRIDE + wn * 64 + tn * 8 + g;
                unsigned bh0 = Bh[bb], bh1 = Bh[bb + 4 * B_STRIDE];
                unsigned bl0 = Bl[bb], bl1 = Bl[bb + 4 * B_STRIDE];
#pragma unroll
                for (int mi = 0; mi < 2; mi++) {
                    mma16(acc[mi][tn], ah[mi], bh0, bh1);   // hi*hi
                    mma16(acc[mi][tn], ah[mi], bl0, bl1);   // hi*lo
                    mma16(acc[mi][tn], al[mi], bh0, bh1);   // lo*hi
                }
            }
        }
    }

    // ---- epilogue ----
    if (PACK) {
        unsigned* ohi = Ohi + (size_t)z * M * (N / 2);
        unsigned* olo = Olo + (size_t)z * M * (N / 2);
#pragma unroll
        for (int mi = 0; mi < 2; mi++) {
            int row = brow + wm * 32 + mi * 16 + g;
#pragma unroll
            for (int tn = 0; tn < 8; tn++) {
                int col = bcol + wn * 64 + tn * 8 + t4 * 2;
                float2 bv = *reinterpret_cast<const float2*>(bias + col);
                float v0 = acc[mi][tn].x + bv.x, v1 = acc[mi][tn].y + bv.y;
                float v2 = acc[mi][tn].z + bv.x, v3 = acc[mi][tn].w + bv.y;
                v0 = 0.5f * v0 * (1.f + erff(v0 * 0.70710678118654752f));
                v1 = 0.5f * v1 * (1.f + erff(v1 * 0.70710678118654752f));
                v2 = 0.5f * v2 * (1.f + erff(v2 * 0.70710678118654752f));
                v3 = 0.5f * v3 * (1.f + erff(v3 * 0.70710678118654752f));
                int col2 = col >> 1;
                unsigned h, l;
                packsplit2(v0, v1, h, l);
                ohi[(size_t)row * (N / 2) + col2] = h;
                olo[(size_t)row * (N / 2) + col2] = l;
                packsplit2(v2, v3, h, l);
                ohi[(size_t)(row + 8) * (N / 2) + col2] = h;
                olo[(size_t)(row + 8) * (N / 2) + col2] = l;
            }
        }
    } else {
        float* C = Cf + (size_t)z * M * N;
#pragma unroll
        for (int mi = 0; mi < 2; mi++) {
            int row = brow + wm * 32 + mi * 16 + g;
#pragma unroll
            for (int tn = 0; tn < 8; tn++) {
                int col = bcol + wn * 64 + tn * 8 + t4 * 2;
                float2 bv = *reinterpret_cast<const float2*>(bias + col);
                float2 v0, v1;
                v0.x = acc[mi][tn].x + bv.x;  v0.y = acc[mi][tn].y + bv.y;
                v1.x = acc[mi][tn].z + bv.x;  v1.y = acc[mi][tn].w + bv.y;
                *reinterpret_cast<float2*>(C + (size_t)row * N + col) = v0;
                *reinterpret_cast<float2*>(C + (size_t)(row + 8) * N + col) = v1;
            }
        }
    }
}

// ---------------- combine -------------------------------------------------------
__global__ void combine_kernel(float* __restrict__ y)
{
    int t = blockIdx.x;
    int e0 = g_idx[t * 2], e1 = g_idx[t * 2 + 1];
    int p0 = g_pos[t * 2], p1 = g_pos[t * 2 + 1];
    float w0 = g_gv[t * 2], w1 = g_gv[t * 2 + 1];
    const float* r0 = (p0 >= 0) ? g_eo + ((size_t)e0 * CAPE + p0) * DM : nullptr;
    const float* r1 = (p1 >= 0) ? g_eo + ((size_t)e1 * CAPE + p1) * DM : nullptr;
    float* yr = y + (size_t)t * DM;
    for (int d = threadIdx.x * 4; d < DM; d += blockDim.x * 4) {
        float4 a = make_float4(0.f, 0.f, 0.f, 0.f);
        if (r0) {
            float4 v = *reinterpret_cast<const float4*>(r0 + d);
            a.x = fmaf(w0, v.x, a.x); a.y = fmaf(w0, v.y, a.y);
            a.z = fmaf(w0, v.z, a.z); a.w = fmaf(w0, v.w, a.w);
        }
        if (r1) {
            float4 v = *reinterpret_cast<const float4*>(r1 + d);
            a.x = fmaf(w1, v.x, a.x); a.y = fmaf(w1, v.y, a.y);
            a.z = fmaf(w1, v.z, a.z); a.w = fmaf(w1, v.w, a.w);
        }
        *reinterpret_cast<float4*>(yr + d) = a;
    }
}

// ---------------- launch ---------------------------------------------------------
extern "C" void kernel_launch(void* const* d_in, const int* in_sizes, int n_in,
                              void* d_out, int out_size)
{
    const float* x    = (const float*)d_in[0];
    const float* wg   = (const float*)d_in[1];
    const float* fc1w = (const float*)d_in[2];
    const float* fc1b = (const float*)d_in[3];
    const float* fc2w = (const float*)d_in[4];
    const float* fc2b = (const float*)d_in[5];
    float* y = (float*)d_out;

    unsigned *dhi, *dlo, *hhi, *hlo, *w1h, *w1l, *w2h, *w2l;
    float* eo;
    cudaGetSymbolAddress((void**)&dhi, g_disp_hi);
    cudaGetSymbolAddress((void**)&dlo, g_disp_lo);
    cudaGetSymbolAddress((void**)&hhi, g_h_hi);
    cudaGetSymbolAddress((void**)&hlo, g_h_lo);
    cudaGetSymbolAddress((void**)&w1h, g_w1hi);
    cudaGetSymbolAddress((void**)&w1l, g_w1lo);
    cudaGetSymbolAddress((void**)&w2h, g_w2hi);
    cudaGetSymbolAddress((void**)&w2l, g_w2lo);
    cudaGetSymbolAddress((void**)&eo,  g_eo);

    cudaFuncSetAttribute(mma_gemm<true>,  cudaFuncAttributeMaxDynamicSharedMemorySize, GEMM_SMEM);
    cudaFuncSetAttribute(mma_gemm<false>, cudaFuncAttributeMaxDynamicSharedMemorySize, GEMM_SMEM);

    // weight packing (hi/lo bf16 planes)
    packw_kernel<<<65536, 256>>>(fc1w, w1h, w1l, DM, HID);
    packw_kernel<<<65536, 256>>>(fc2w, w2h, w2l, HID, DM);

    gate_kernel<<<STOK / 8, 256>>>(x, wg);
    pos_kernel<<<NE, 1024>>>();
    dispatch_kernel<<<STOK * 2, 256>>>(x);

    dim3 g1(HID / 128, CAPE / 128, NE);   // fc1 + gelu -> packed h
    mma_gemm<true><<<g1, 256, GEMM_SMEM>>>(dhi, dlo, w1h, w1l, fc1b,
                                           nullptr, hhi, hlo, CAPE, HID, DM / 2);

    dim3 g2(DM / 128, CAPE / 128, NE);    // fc2 -> fp32 eo
    mma_gemm<false><<<g2, 256, GEMM_SMEM>>>(hhi, hlo, w2h, w2l, fc2b,
                                            eo, nullptr, nullptr, CAPE, DM, HID / 2);

    combine_kernel<<<STOK, 256>>>(y);
}